// round 9
// baseline (speedup 1.0000x reference)
#include <cuda_runtime.h>
#include <cstdint>

// Problem shape (fixed by the dataset instance)
#define BB   2
#define HH   32
#define SS   4096
#define DD   128
#define BLK  512
#define NB   (SS / BLK)          // 8
#define NCTA (BB * HH * NB)      // 512
#define NT   256
#define EPS_F 1e-6f

// Layout strides (floats)
#define KPAD 168   // phiK stage row stride, pe-permuted cols  (168 % 32 == 8)
#define VPAD 136   // V stage row stride, plain cols            (136 % 32 == 8)
#define QPAD 136   // phiQ stage row stride, pd-permuted cols
#define MPAD 136   // Sdm_T row stride (m-major), pd-permuted d

// pe(d) = (d&7)*18 + (d>>3)   : phiK column permutation (max 141 < 168)
// pd(c) = (c&3)*34 + (c>>2)   : phiQ / Sdm_T column permutation (max 133 < 136)

// Shared layout (floats):
//  Sdm_T : 136 rows (m; 128 = Z, 129..135 zero) x MPAD      -> 18496
//  stage : p1 = 2 x (16*KPAD phiK + 16*VPAD V) = 9728 ; p2 = 64*QPAD phiQ (8704)
//  den   : 64
#define SDMT_OFF  0
#define STAGE_OFF (136 * MPAD)                 // 18496
#define BUF_FLOATS (16 * KPAD + 16 * VPAD)     // 4864
#define DEN_OFF   (STAGE_OFF + 2 * BUF_FLOATS) // 28224
#define SMEM_FLOATS (DEN_OFF + 64)             // 28288
#define SMEM_BYTES  (SMEM_FLOATS * 4)          // 113152 -> 2 CTAs/SM

__device__ __forceinline__ float phi_elu1(float y) {
    return y > 0.0f ? y + 1.0f : __expf(y);
}

__device__ __forceinline__ uint32_t f2tf(float x) {
    uint32_t u;
    asm("cvt.rna.tf32.f32 %0, %1;" : "=r"(u) : "f"(x));
    return u;
}

__device__ __forceinline__ void mma_tf32(float* c, const uint32_t* a, const uint32_t* b) {
    asm volatile(
        "mma.sync.aligned.m16n8k8.row.col.f32.tf32.tf32.f32 "
        "{%0,%1,%2,%3}, {%4,%5,%6,%7}, {%8,%9}, {%0,%1,%2,%3};\n"
        : "+f"(c[0]), "+f"(c[1]), "+f"(c[2]), "+f"(c[3])
        : "r"(a[0]), "r"(a[1]), "r"(a[2]), "r"(a[3]), "r"(b[0]), "r"(b[1]));
}

extern "C" __global__ void __launch_bounds__(NT, 2)
lin_attn_tc4(const float* __restrict__ q,
             const float* __restrict__ k,
             const float* __restrict__ v,
             const float* __restrict__ sc,
             const float* __restrict__ bi,
             float* __restrict__ out)
{
    extern __shared__ float sm[];
    float* SdmT  = sm + SDMT_OFF;      // [136][MPAD] m-major, pd-permuted
    float* stage = sm + STAGE_OFF;
    float* den   = sm + DEN_OFF;

    const int tid  = threadIdx.x;
    const int lane = tid & 31;
    const int w    = tid >> 5;          // warp 0..7
    const int g    = lane >> 2;         // 0..7
    const int t    = lane & 3;          // 0..3

    const int c  = blockIdx.x;
    const int n  = c % NB;
    const int bh = c / NB;
    const int h  = bh % HH;
    const long gbase = ((long)bh * SS + (long)n * BLK) * DD;

    const float* qb = q + gbase;
    const float* kb = k + gbase;
    const float* vb = v + gbase;
    float*       ob = out + gbase;

    const int lrow = w;                 // loader row 0..7
    const int c4   = lane * 4;          // loader column group
    const float4 sc4 = *(const float4*)(sc + h * DD + c4);
    const float4 bi4 = *(const float4*)(bi + h * DD + c4);

    // pe base for phiK producer scatter: col = 4*lane + j -> pe = 72*(lane&1) + 18*j + (lane>>1)
    const int pe_base = 72 * (lane & 1) + (lane >> 1);

    // ================= Phase 1: S = phi(K)^T V ; Z = sum phi(K) =============
    // warp tiling: wd in {0,1} -> 64 d-rows; wm1 in {0..3} -> 32 m-cols
    const int wd  = w & 1;
    const int wm1 = w >> 1;

    float acc[4][4][4];
    #pragma unroll
    for (int a = 0; a < 4; ++a)
        #pragma unroll
        for (int b = 0; b < 4; ++b)
            #pragma unroll
            for (int r = 0; r < 4; ++r) acc[a][b][r] = 0.0f;

    float4 zacc = make_float4(0.f, 0.f, 0.f, 0.f);
    float4 kv[2], vv[2];

#define LOADCH(ch) do {                                                     \
        const float* kc_ = kb + (long)(ch) * 16 * DD;                       \
        const float* vc_ = vb + (long)(ch) * 16 * DD;                       \
        kv[0] = *(const float4*)(kc_ + (long)lrow * DD + c4);               \
        kv[1] = *(const float4*)(kc_ + (long)(lrow + 8) * DD + c4);         \
        vv[0] = *(const float4*)(vc_ + (long)lrow * DD + c4);               \
        vv[1] = *(const float4*)(vc_ + (long)(lrow + 8) * DD + c4);         \
    } while (0)

    // phiK scattered into pe layout (4x STS.32); V stored plain (1x STS.128)
#define STORECH(pk_, pv_) do {                                              \
        _Pragma("unroll")                                                   \
        for (int j_ = 0; j_ < 2; ++j_) {                                    \
            const int r_ = lrow + 8 * j_;                                   \
            float p0 = phi_elu1(fmaf(kv[j_].x, sc4.x, bi4.x));              \
            float p1 = phi_elu1(fmaf(kv[j_].y, sc4.y, bi4.y));              \
            float p2 = phi_elu1(fmaf(kv[j_].z, sc4.z, bi4.z));              \
            float p3 = phi_elu1(fmaf(kv[j_].w, sc4.w, bi4.w));              \
            zacc.x += p0; zacc.y += p1; zacc.z += p2; zacc.w += p3;         \
            float* kr_ = (pk_) + r_ * KPAD + pe_base;                       \
            *(uint32_t*)(kr_ + 0)  = f2tf(p0);                              \
            *(uint32_t*)(kr_ + 18) = f2tf(p1);                              \
            *(uint32_t*)(kr_ + 36) = f2tf(p2);                              \
            *(uint32_t*)(kr_ + 54) = f2tf(p3);                              \
            uint4 vu_ = make_uint4(f2tf(vv[j_].x), f2tf(vv[j_].y),          \
                                   f2tf(vv[j_].z), f2tf(vv[j_].w));         \
            *(uint4*)((pv_) + r_ * VPAD + c4) = vu_;                        \
        }                                                                   \
    } while (0)

    LOADCH(0);
    STORECH(stage, stage + 16 * KPAD);
    LOADCH(1);
    __syncthreads();

    for (int ch = 0; ch < BLK / 16; ++ch) {
        const int p = ch & 1;
        float* pk = stage + p * BUF_FLOATS;
        float* pv = pk + 16 * KPAD;

        if (ch < BLK / 16 - 1) {
            float* npk = stage + (p ^ 1) * BUF_FLOATS;
            STORECH(npk, npk + 16 * KPAD);
        }
        if (ch < BLK / 16 - 2) LOADCH(ch + 2);

        #pragma unroll
        for (int ks = 0; ks < 2; ++ks) {
            const int sb = ks * 8;
            // B fragments (V), scalar (proven conflict-free: bank 8t+g)
            uint32_t B[4][2];
            #pragma unroll
            for (int mt = 0; mt < 4; ++mt) {
                const int m = wm1 * 32 + mt * 8 + g;
                B[mt][0] = __float_as_uint(pv[(sb + t) * VPAD + m]);
                B[mt][1] = __float_as_uint(pv[(sb + t + 4) * VPAD + m]);
            }
            // A fragments via v2 from pe layout: pe(d0+g)=18g+wd*8+2dt, +1 for d+8
            const float* a_lo = pk + (sb + t)     * KPAD + 18 * g + wd * 8;
            const float* a_hi = pk + (sb + t + 4) * KPAD + 18 * g + wd * 8;
            #pragma unroll
            for (int dt = 0; dt < 4; ++dt) {
                const float2 a01 = *(const float2*)(a_lo + 2 * dt);
                const float2 a23 = *(const float2*)(a_hi + 2 * dt);
                uint32_t A[4] = { __float_as_uint(a01.x), __float_as_uint(a01.y),
                                  __float_as_uint(a23.x), __float_as_uint(a23.y) };
                #pragma unroll
                for (int mt = 0; mt < 4; ++mt)
                    mma_tf32(acc[dt][mt], A, B[mt]);
            }
        }
        __syncthreads();
    }

    // ===== write S into Sdm_T (m-major, pd-permuted d), as tf32 =====
    // frag: c0=(d0+g, m), c1=(d0+g, m+1), c2=(d0+g+8, m), c3=(d0+g+8, m+1); m=wm1*32+8mt+2t
    #pragma unroll
    for (int dt = 0; dt < 4; ++dt) {
        // pd(d0+g) = 34*(g&3) + wd*16 + dt*4 + (g>>2); pd(d0+g+8) = +2
        const int pdg = 34 * (g & 3) + wd * 16 + dt * 4 + (g >> 2);
        #pragma unroll
        for (int mt = 0; mt < 4; ++mt) {
            const int m = wm1 * 32 + mt * 8 + 2 * t;
            *(uint32_t*)(SdmT + m       * MPAD + pdg)     = f2tf(acc[dt][mt][0]);
            *(uint32_t*)(SdmT + (m + 1) * MPAD + pdg)     = f2tf(acc[dt][mt][1]);
            *(uint32_t*)(SdmT + m       * MPAD + pdg + 2) = f2tf(acc[dt][mt][2]);
            *(uint32_t*)(SdmT + (m + 1) * MPAD + pdg + 2) = f2tf(acc[dt][mt][3]);
        }
    }

    // prefetch Q chunk 0 (overlaps Z reduction)
    float4 qreg[8];
    #pragma unroll
    for (int j = 0; j < 8; ++j)
        qreg[j] = *(const float4*)(qb + (long)(lrow + 8 * j) * DD + c4);

    // reduce Z -> Sdm_T row 128 ; zero rows 129..135
    float* zred = stage;   // reuse stage region (phase-1 data dead after sync)
    __syncthreads();
    *(float4*)(zred + lrow * DD + c4) = zacc;
    __syncthreads();
    if (tid < DD) {
        float s = 0.0f;
        #pragma unroll
        for (int r = 0; r < 8; ++r) s += zred[r * DD + tid];
        *(uint32_t*)(SdmT + 128 * MPAD + (tid & 3) * 34 + (tid >> 2)) = f2tf(s);
    }
    for (int idx = tid; idx < 7 * MPAD; idx += NT)
        SdmT[129 * MPAD + idx] = 0.0f;
    __syncthreads();

    // ===== Phase 2: out = phi(Q) [S | Z] ; den fused as m-row 128 ==========
    // chunk = 64 s-rows; warp grid 2s x 4m: tile 32s x 32m
    const int ws = w & 1;
    const int wm = w >> 1;
    const int s0 = ws * 32;
    const int m0 = wm * 32;

    for (int chq = 0; chq < BLK / 64; ++chq) {
        // stage phi(Q) into pd layout: col 4*lane+j -> word 34*j + lane (coalesced STS.32)
        #pragma unroll
        for (int j = 0; j < 8; ++j) {
            const int r = lrow + 8 * j;
            float p0 = phi_elu1(fmaf(qreg[j].x, sc4.x, bi4.x));
            float p1 = phi_elu1(fmaf(qreg[j].y, sc4.y, bi4.y));
            float p2 = phi_elu1(fmaf(qreg[j].z, sc4.z, bi4.z));
            float p3 = phi_elu1(fmaf(qreg[j].w, sc4.w, bi4.w));
            float* qr = stage + r * QPAD + lane;
            *(uint32_t*)(qr + 0)   = f2tf(p0);
            *(uint32_t*)(qr + 34)  = f2tf(p1);
            *(uint32_t*)(qr + 68)  = f2tf(p2);
            *(uint32_t*)(qr + 102) = f2tf(p3);
        }
        __syncthreads();

        // prefetch next Q chunk (overlaps mma)
        if (chq < BLK / 64 - 1) {
            const float* qc = qb + (long)(chq + 1) * 64 * DD;
            #pragma unroll
            for (int j = 0; j < 8; ++j)
                qreg[j] = *(const float4*)(qc + (long)(lrow + 8 * j) * DD + c4);
        }

        // GEMM: warp 32s x 32m (+ Z row for wm==0), K = 128
        float accq[2][5][4];
        #pragma unroll
        for (int st = 0; st < 2; ++st)
            #pragma unroll
            for (int mt = 0; mt < 5; ++mt)
                #pragma unroll
                for (int r = 0; r < 4; ++r) accq[st][mt][r] = 0.0f;

        #pragma unroll
        for (int kk = 0; kk < DD / 8; ++kk) {
            const int pw = 34 * t + 2 * kk;   // pd word for cols (8kk+t, 8kk+t+4)
            uint32_t A[2][4];
            #pragma unroll
            for (int st = 0; st < 2; ++st) {
                const int row = s0 + st * 16;
                const float2 alo = *(const float2*)(stage + (row + g)     * QPAD + pw);
                const float2 ahi = *(const float2*)(stage + (row + g + 8) * QPAD + pw);
                A[st][0] = __float_as_uint(alo.x);   // (row+g,   8kk+t)
                A[st][1] = __float_as_uint(ahi.x);   // (row+g+8, 8kk+t)
                A[st][2] = __float_as_uint(alo.y);   // (row+g,   8kk+t+4)
                A[st][3] = __float_as_uint(ahi.y);   // (row+g+8, 8kk+t+4)
            }
            #pragma unroll
            for (int mt = 0; mt < 4; ++mt) {
                const int m = m0 + mt * 8 + g;
                const float2 bf = *(const float2*)(SdmT + m * MPAD + pw);
                uint32_t B[2] = { __float_as_uint(bf.x), __float_as_uint(bf.y) };
                mma_tf32(accq[0][mt], A[0], B);
                mma_tf32(accq[1][mt], A[1], B);
            }
            if (wm == 0) {
                const float2 bf = *(const float2*)(SdmT + (128 + g) * MPAD + pw);
                uint32_t B[2] = { __float_as_uint(bf.x), __float_as_uint(bf.y) };
                mma_tf32(accq[0][4], A[0], B);
                mma_tf32(accq[1][4], A[1], B);
            }
        }

        // den = Z-row result (n=0 of Z tile -> lanes t==0, c0/c2)
        if (wm == 0 && t == 0) {
            #pragma unroll
            for (int st = 0; st < 2; ++st) {
                den[s0 + st * 16 + g]     = accq[st][4][0] + EPS_F;
                den[s0 + st * 16 + g + 8] = accq[st][4][2] + EPS_F;
            }
        }
        __syncthreads();   // den visible; stage reads complete

        // epilogue: scale by 1/den, store
        #pragma unroll
        for (int st = 0; st < 2; ++st) {
            const int rr   = s0 + st * 16 + g;
            const int r0   = chq * 64 + rr;
            const float i0 = 1.0f / den[rr];
            const float i1 = 1.0f / den[rr + 8];
            #pragma unroll
            for (int mt = 0; mt < 4; ++mt) {
                const int m = m0 + mt * 8 + 2 * t;
                *(float2*)(ob + (long)r0 * DD + m) =
                    make_float2(accq[st][mt][0] * i0, accq[st][mt][1] * i0);
                *(float2*)(ob + (long)(r0 + 8) * DD + m) =
                    make_float2(accq[st][mt][2] * i1, accq[st][mt][3] * i1);
            }
        }
    }
}

extern "C" void kernel_launch(void* const* d_in, const int* in_sizes, int n_in,
                              void* d_out, int out_size) {
    const float* q  = (const float*)d_in[0];
    const float* k  = (const float*)d_in[1];
    const float* v  = (const float*)d_in[2];
    const float* sc = (const float*)d_in[3];
    const float* bi = (const float*)d_in[4];
    float* out = (float*)d_out;

    cudaFuncSetAttribute(lin_attn_tc4,
                         cudaFuncAttributeMaxDynamicSharedMemorySize, SMEM_BYTES);
    lin_attn_tc4<<<NCTA, NT, SMEM_BYTES>>>(q, k, v, sc, bi, out);
}

// round 10
// speedup vs baseline: 1.4248x; 1.4248x over previous
#include <cuda_runtime.h>
#include <cuda_fp16.h>
#include <cstdint>

// Problem shape (fixed by the dataset instance)
#define BB   2
#define HH   32
#define SS   4096
#define DD   128
#define BLK  512
#define NB   (SS / BLK)          // 8
#define NCTA (BB * HH * NB)      // 512
#define NT   256
#define EPS_F 1e-6f

// Smem word strides (4B words, each word = half2 pair along the k dim)
//  W  (phiK pairs)  : [8][KSTR]  bank(4t+g) conflict-free   KSTR%32 == 4
//  WV (V pairs)     : [8][VSTR]  bank(8t+g) conflict-free   VSTR%32 == 8
//  WQ (phiQ words)  : [64][QSTR] bank(4g+t) conflict-free   QSTR%32 == 4
//  WS (Sdm pairs)   : [64][MSTR] bank(8t+g) conflict-free   MSTR%32 == 8
#define KSTR 132
#define VSTR 136
#define QSTR 68
#define MSTR 136

#define WS_OFF    0                        // 64 x 136 = 8704 words
#define STAGE_OFF (64 * MSTR)              // 8704
#define BUF_WORDS (8 * KSTR + 8 * VSTR)    // 2144 (phase-1, x2 buffers = 4288)
#define DEN_OFF   (STAGE_OFF + 64 * QSTR)  // 8704 + 4352 = 13056 (WQ >= 2 bufs)
#define SMEM_WORDS (DEN_OFF + 64)          // 13120
#define SMEM_BYTES (SMEM_WORDS * 4)        // 52480 B -> 2 CTAs/SM (reg-bound)

__device__ __forceinline__ float phi_elu1(float y) {
    return y > 0.0f ? y + 1.0f : __expf(y);
}

__device__ __forceinline__ uint32_t pk2(float lo, float hi) {
    __half2 h = __floats2half2_rn(lo, hi);
    return *reinterpret_cast<uint32_t*>(&h);
}

__device__ __forceinline__ void mma_f16(float* c, const uint32_t* a, const uint32_t* b) {
    asm volatile(
        "mma.sync.aligned.m16n8k16.row.col.f32.f16.f16.f32 "
        "{%0,%1,%2,%3}, {%4,%5,%6,%7}, {%8,%9}, {%0,%1,%2,%3};\n"
        : "+f"(c[0]), "+f"(c[1]), "+f"(c[2]), "+f"(c[3])
        : "r"(a[0]), "r"(a[1]), "r"(a[2]), "r"(a[3]), "r"(b[0]), "r"(b[1]));
}

extern "C" __global__ void __launch_bounds__(NT, 2)
lin_attn_fp16(const float* __restrict__ q,
              const float* __restrict__ k,
              const float* __restrict__ v,
              const float* __restrict__ sc,
              const float* __restrict__ bi,
              float* __restrict__ out)
{
    extern __shared__ uint32_t sm[];
    uint32_t* WS    = sm + WS_OFF;      // Sdm pairs [64][MSTR]; col 128 = Z, 129..135 = 0
    uint32_t* stage = sm + STAGE_OFF;   // phase1: 2 x (W + WV); phase2: WQ
    float*    den   = (float*)(sm + DEN_OFF);

    const int tid  = threadIdx.x;
    const int lane = tid & 31;
    const int w    = tid >> 5;          // warp 0..7
    const int g    = lane >> 2;         // 0..7
    const int t    = lane & 3;          // 0..3

    const int c  = blockIdx.x;
    const int n  = c % NB;
    const int bh = c / NB;
    const int h  = bh % HH;
    const long gbase = ((long)bh * SS + (long)n * BLK) * DD;

    const float* qb = q + gbase;
    const float* kb = k + gbase;
    const float* vb = v + gbase;
    float*       ob = out + gbase;

    const int lrow = w;                 // producer handles s-row pair (2w, 2w+1)
    const int c4   = lane * 4;          // producer d-columns c4..c4+3
    const float4 sc4 = *(const float4*)(sc + h * DD + c4);
    const float4 bi4 = *(const float4*)(bi + h * DD + c4);

    // ====== Phase 1: S^T[m][d] = V^T x phiK  (A = V^T, B = phiK, k = s) ====
    // warp tiling: wa = m half (64), wb = d quarter (32)
    const int wa = w & 1;
    const int wb = w >> 1;

    float acc[4][4][4];                 // [mt][dt][c]
    #pragma unroll
    for (int a = 0; a < 4; ++a)
        #pragma unroll
        for (int b = 0; b < 4; ++b)
            #pragma unroll
            for (int r = 0; r < 4; ++r) acc[a][b][r] = 0.0f;

    float4 zacc = make_float4(0.f, 0.f, 0.f, 0.f);
    float4 kv0, kv1, vv0, vv1;

#define LOADCH(ch) do {                                                     \
        const float* kc_ = kb + (long)((ch) * 16 + 2 * lrow) * DD;          \
        const float* vc_ = vb + (long)((ch) * 16 + 2 * lrow) * DD;          \
        kv0 = *(const float4*)(kc_ + c4);                                   \
        kv1 = *(const float4*)(kc_ + DD + c4);                              \
        vv0 = *(const float4*)(vc_ + c4);                                   \
        vv1 = *(const float4*)(vc_ + DD + c4);                              \
    } while (0)

    // pack half2(s-row 2p, s-row 2p+1) per d column; one uint4 store each
#define STORECH(pk_, pv_) do {                                              \
        float a0 = phi_elu1(fmaf(kv0.x, sc4.x, bi4.x));                     \
        float a1 = phi_elu1(fmaf(kv0.y, sc4.y, bi4.y));                     \
        float a2 = phi_elu1(fmaf(kv0.z, sc4.z, bi4.z));                     \
        float a3 = phi_elu1(fmaf(kv0.w, sc4.w, bi4.w));                     \
        float b0 = phi_elu1(fmaf(kv1.x, sc4.x, bi4.x));                     \
        float b1 = phi_elu1(fmaf(kv1.y, sc4.y, bi4.y));                     \
        float b2 = phi_elu1(fmaf(kv1.z, sc4.z, bi4.z));                     \
        float b3 = phi_elu1(fmaf(kv1.w, sc4.w, bi4.w));                     \
        zacc.x += a0 + b0; zacc.y += a1 + b1;                               \
        zacc.z += a2 + b2; zacc.w += a3 + b3;                               \
        uint4 ku_ = make_uint4(pk2(a0, b0), pk2(a1, b1),                    \
                               pk2(a2, b2), pk2(a3, b3));                   \
        *(uint4*)((pk_) + lrow * KSTR + c4) = ku_;                          \
        uint4 vu_ = make_uint4(pk2(vv0.x, vv1.x), pk2(vv0.y, vv1.y),        \
                               pk2(vv0.z, vv1.z), pk2(vv0.w, vv1.w));       \
        *(uint4*)((pv_) + lrow * VSTR + c4) = vu_;                          \
    } while (0)

    LOADCH(0);
    STORECH(stage, stage + 8 * KSTR);
    LOADCH(1);
    __syncthreads();

    for (int ch = 0; ch < BLK / 16; ++ch) {
        const int p = ch & 1;
        uint32_t* pk = stage + p * BUF_WORDS;
        uint32_t* pv = pk + 8 * KSTR;

        if (ch < BLK / 16 - 1) {
            uint32_t* npk = stage + (p ^ 1) * BUF_WORDS;
            STORECH(npk, npk + 8 * KSTR);
        }
        if (ch < BLK / 16 - 2) LOADCH(ch + 2);

        // one k=16 step over the 16 staged s-rows
        // B fragments (phiK): b0 = W[t][d], b1 = W[t+4][d]
        uint32_t B[4][2];
        #pragma unroll
        for (int dt = 0; dt < 4; ++dt) {
            const int d = wb * 32 + dt * 8 + g;
            B[dt][0] = pk[t * KSTR + d];
            B[dt][1] = pk[(t + 4) * KSTR + d];
        }
        #pragma unroll
        for (int mt = 0; mt < 4; ++mt) {
            const int m = wa * 64 + mt * 16 + g;
            uint32_t A[4];
            A[0] = pv[t * VSTR + m];            // rows (2t,2t+1), col m
            A[1] = pv[t * VSTR + m + 8];        // col m+8  (A row g+8)
            A[2] = pv[(t + 4) * VSTR + m];      // rows (2t+8,2t+9)
            A[3] = pv[(t + 4) * VSTR + m + 8];
            #pragma unroll
            for (int dt = 0; dt < 4; ++dt)
                mma_f16(acc[mt][dt], A, B[dt]);
        }
        __syncthreads();
    }

    // ===== epilogue: S^T tiles -> WS[d/2][m] as half2 pairs along d =====
    // c0,c1 = (m_row, d=2t, 2t+1): one half2 word at dp = dbase/2 + t
    #pragma unroll
    for (int mt = 0; mt < 4; ++mt) {
        const int m = wa * 64 + mt * 16 + g;
        #pragma unroll
        for (int dt = 0; dt < 4; ++dt) {
            const int dp = wb * 16 + dt * 4 + t;
            WS[dp * MSTR + m]     = pk2(acc[mt][dt][0], acc[mt][dt][1]);
            WS[dp * MSTR + m + 8] = pk2(acc[mt][dt][2], acc[mt][dt][3]);
        }
    }

    // prefetch Q chunk 0 (overlaps Z reduction)
    float4 qreg[8];
    #pragma unroll
    for (int j = 0; j < 8; ++j)
        qreg[j] = *(const float4*)(qb + (long)(lrow + 8 * j) * DD + c4);

    // reduce Z -> WS column 128 ; zero columns 129..135
    float* zred = (float*)stage;        // 8 x 128 floats (phase-1 bufs dead)
    *(float4*)(zred + lrow * DD + c4) = zacc;
    __syncthreads();
    if (tid < 64) {
        float s0 = 0.0f, s1 = 0.0f;
        #pragma unroll
        for (int r = 0; r < 8; ++r) {
            s0 += zred[r * DD + 2 * tid];
            s1 += zred[r * DD + 2 * tid + 1];
        }
        WS[tid * MSTR + 128] = pk2(s0, s1);
    }
    for (int idx = tid; idx < 64 * 7; idx += NT) {
        const int dp = idx / 7;
        const int cc = 129 + idx % 7;
        WS[dp * MSTR + cc] = 0u;
    }
    __syncthreads();

    // ====== Phase 2: out = phiQ x [Sdm | Z] ; den fused as column 128 ======
    // chunk = 64 s-rows; warp grid 2s x 4m (+ Z tile for wm==0)
    uint32_t* WQ = stage;               // [64][QSTR] half2 words along d
    const int ws = w & 1;
    const int wm = w >> 1;
    const int s0 = ws * 32;
    const int m0 = wm * 32;

    for (int chq = 0; chq < BLK / 64; ++chq) {
        // stage phiQ: row r, d c4..c4+3 -> words 2*lane, 2*lane+1 (uint2)
        #pragma unroll
        for (int j = 0; j < 8; ++j) {
            const int r = lrow + 8 * j;
            float p0 = phi_elu1(fmaf(qreg[j].x, sc4.x, bi4.x));
            float p1 = phi_elu1(fmaf(qreg[j].y, sc4.y, bi4.y));
            float p2 = phi_elu1(fmaf(qreg[j].z, sc4.z, bi4.z));
            float p3 = phi_elu1(fmaf(qreg[j].w, sc4.w, bi4.w));
            uint2 qu = make_uint2(pk2(p0, p1), pk2(p2, p3));
            *(uint2*)(WQ + r * QSTR + 2 * lane) = qu;
        }
        __syncthreads();

        // prefetch next Q chunk (overlaps mma)
        if (chq < BLK / 64 - 1) {
            const float* qc = qb + (long)(chq + 1) * 64 * DD;
            #pragma unroll
            for (int j = 0; j < 8; ++j)
                qreg[j] = *(const float4*)(qc + (long)(lrow + 8 * j) * DD + c4);
        }

        float accq[2][5][4];
        #pragma unroll
        for (int st = 0; st < 2; ++st)
            #pragma unroll
            for (int mt = 0; mt < 5; ++mt)
                #pragma unroll
                for (int r = 0; r < 4; ++r) accq[st][mt][r] = 0.0f;

        #pragma unroll
        for (int kk = 0; kk < DD / 16; ++kk) {       // 8 k-steps of 16
            uint32_t A[2][4];
            #pragma unroll
            for (int st = 0; st < 2; ++st) {
                const int row = s0 + st * 16;
                A[st][0] = WQ[(row + g)     * QSTR + 8 * kk + t];
                A[st][1] = WQ[(row + g + 8) * QSTR + 8 * kk + t];
                A[st][2] = WQ[(row + g)     * QSTR + 8 * kk + t + 4];
                A[st][3] = WQ[(row + g + 8) * QSTR + 8 * kk + t + 4];
            }
            #pragma unroll
            for (int mt = 0; mt < 4; ++mt) {
                const int m = m0 + mt * 8 + g;
                uint32_t B[2];
                B[0] = WS[(8 * kk + t)     * MSTR + m];
                B[1] = WS[(8 * kk + t + 4) * MSTR + m];
                mma_f16(accq[0][mt], A[0], B);
                mma_f16(accq[1][mt], A[1], B);
            }
            if (wm == 0) {
                uint32_t B[2];
                B[0] = WS[(8 * kk + t)     * MSTR + 128 + g];
                B[1] = WS[(8 * kk + t + 4) * MSTR + 128 + g];
                mma_f16(accq[0][4], A[0], B);
                mma_f16(accq[1][4], A[1], B);
            }
        }

        // den = Z-tile col 128 (t==0: c0 row g, c2 row g+8)
        if (wm == 0 && t == 0) {
            #pragma unroll
            for (int st = 0; st < 2; ++st) {
                den[s0 + st * 16 + g]     = accq[st][4][0] + EPS_F;
                den[s0 + st * 16 + g + 8] = accq[st][4][2] + EPS_F;
            }
        }
        __syncthreads();   // den visible; WQ reads complete before restage

        // epilogue: scale by 1/den, store
        #pragma unroll
        for (int st = 0; st < 2; ++st) {
            const int rr   = s0 + st * 16 + g;
            const int r0   = chq * 64 + rr;
            const float i0 = 1.0f / den[rr];
            const float i1 = 1.0f / den[rr + 8];
            #pragma unroll
            for (int mt = 0; mt < 4; ++mt) {
                const int m = m0 + mt * 8 + 2 * t;
                *(float2*)(ob + (long)r0 * DD + m) =
                    make_float2(accq[st][mt][0] * i0, accq[st][mt][1] * i0);
                *(float2*)(ob + (long)(r0 + 8) * DD + m) =
                    make_float2(accq[st][mt][2] * i1, accq[st][mt][3] * i1);
            }
        }
    }
}

extern "C" void kernel_launch(void* const* d_in, const int* in_sizes, int n_in,
                              void* d_out, int out_size) {
    const float* q  = (const float*)d_in[0];
    const float* k  = (const float*)d_in[1];
    const float* v  = (const float*)d_in[2];
    const float* sc = (const float*)d_in[3];
    const float* bi = (const float*)d_in[4];
    float* out = (float*)d_out;

    cudaFuncSetAttribute(lin_attn_fp16,
                         cudaFuncAttributeMaxDynamicSharedMemorySize, SMEM_BYTES);
    lin_attn_fp16<<<NCTA, NT, SMEM_BYTES>>>(q, k, v, sc, bi, out);
}